// round 6
// baseline (speedup 1.0000x reference)
#include <cuda_runtime.h>
#include <cstdint>

#define T_SEQ 2048
#define NBATCH 64
#define NIN 16
#define NHEAD 8
#define HID 64
#define NGATE 256

// h history scratch (device global; no runtime allocation)
__device__ float g_hist[(size_t)T_SEQ * NBATCH * NHEAD * HID];   // 256 MB

// ---- tf32 helpers ----
__device__ __forceinline__ void tf32_split(float f, uint32_t& hi, uint32_t& lo) {
    asm("cvt.rna.tf32.f32 %0, %1;" : "=r"(hi) : "f"(f));
    float rem = f - __uint_as_float(hi);
    asm("cvt.rna.tf32.f32 %0, %1;" : "=r"(lo) : "f"(rem));
}
__device__ __forceinline__ void mma1688(float& d0, float& d1, float& d2, float& d3,
                                        uint32_t a0, uint32_t a1, uint32_t a2, uint32_t a3,
                                        uint32_t b0, uint32_t b1) {
    asm volatile(
        "mma.sync.aligned.m16n8k8.row.col.f32.tf32.tf32.f32 "
        "{%0,%1,%2,%3},{%4,%5,%6,%7},{%8,%9},{%0,%1,%2,%3};"
        : "+f"(d0), "+f"(d1), "+f"(d2), "+f"(d3)
        : "r"(a0), "r"(a1), "r"(a2), "r"(a3), "r"(b0), "r"(b1));
}
__device__ __forceinline__ float sigf(float z) {
    return __fdividef(1.0f, 1.0f + __expf(-z));
}
__device__ __forceinline__ float tanhf_fast(float z) {
    return fmaf(2.0f, sigf(2.0f * z), -1.0f);
}

// ============================================================================
// Recurrent kernel, tf32 tensor-core version.
// Grid: 64 CTAs = head(8) x batch-group(8 batches). Block: 512 (16 warps).
// Warp w owns gate-row tile [w*16, w*16+16). Per step:
//   Z[256,8] = Whh[256,64]@h[64,8] + Wih[256,16]@x[16,8]   (10 k-steps of k8)
// 3-term tf32 split (Whi·Bhi + Whi·Blo + Wlo·Bhi), fp32 accumulate.
// A-fragments (weights) register-resident: 10 ks x {hi,lo} x 4 = 80 regs.
// Consumers: 512 threads = 512 (batch,hid) cells, c in register.
// ============================================================================
__global__ __launch_bounds__(512, 1) void lstm_rec_mma(
    const float* __restrict__ x,     // (T,B,16)
    const float* __restrict__ W_ih,  // (8,256,16)
    const float* __restrict__ W_hh,  // (8,256,64)
    const float* __restrict__ b_ih,  // (8,256)
    const float* __restrict__ b_hh)  // (8,256)
{
    const int tid  = threadIdx.x;
    const int wid  = tid >> 5;          // warp = M-tile 0..15
    const int lane = tid & 31;
    const int g    = lane >> 2;         // group id (row-in-tile / batch col)
    const int tg   = lane & 3;          // thread-in-group (k col / out col pair)
    const int hd   = blockIdx.x >> 3;
    const int b0   = (blockIdx.x & 7) * 8;

    // ---- A fragments (weights), tf32 hi/lo, register resident ----
    uint32_t ahi[10][4], alo[10][4];
    {
        const float* Wh = W_hh + ((size_t)hd * NGATE + wid * 16) * HID;
#pragma unroll
        for (int ks = 0; ks < 8; ++ks) {
            int c0 = ks * 8 + tg, c1 = ks * 8 + tg + 4;
            tf32_split(Wh[g * HID + c0],       ahi[ks][0], alo[ks][0]);
            tf32_split(Wh[(g + 8) * HID + c0], ahi[ks][1], alo[ks][1]);
            tf32_split(Wh[g * HID + c1],       ahi[ks][2], alo[ks][2]);
            tf32_split(Wh[(g + 8) * HID + c1], ahi[ks][3], alo[ks][3]);
        }
        const float* Wi = W_ih + ((size_t)hd * NGATE + wid * 16) * NIN;
#pragma unroll
        for (int ks = 8; ks < 10; ++ks) {
            int c0 = (ks - 8) * 8 + tg, c1 = (ks - 8) * 8 + tg + 4;
            tf32_split(Wi[g * NIN + c0],       ahi[ks][0], alo[ks][0]);
            tf32_split(Wi[(g + 8) * NIN + c0], ahi[ks][1], alo[ks][1]);
            tf32_split(Wi[g * NIN + c1],       ahi[ks][2], alo[ks][2]);
            tf32_split(Wi[(g + 8) * NIN + c1], ahi[ks][3], alo[ks][3]);
        }
    }

    // ---- consumer setup: thread = one (batch, hid) cell ----
    const int jj = tid & 63;            // hid index
    const int bA = tid >> 6;            // batch 0..7 within group
    const float bias_i = b_ih[hd * NGATE + jj]       + b_hh[hd * NGATE + jj];
    const float bias_f = b_ih[hd * NGATE + 64 + jj]  + b_hh[hd * NGATE + 64 + jj];
    const float bias_g = b_ih[hd * NGATE + 128 + jj] + b_hh[hd * NGATE + 128 + jj];
    const float bias_o = b_ih[hd * NGATE + 192 + jj] + b_hh[hd * NGATE + 192 + jj];

    __shared__ float hsm[HID][9];                 // h[k][batch], pad 9 (conflict-free consumer STS)
    __shared__ float xsm[2][NIN][9];              // double-buffered x[feat][batch]
    __shared__ __align__(8) float zsm[NGATE][10]; // z[gate_row][batch], pad 10 (float2-aligned)

    for (int i = tid; i < HID * 9; i += 512) (&hsm[0][0])[i] = 0.0f;

    // x prefetch: 128 threads cover x[t, b0..b0+7, 0..15] (128 contiguous floats)
    float xnext = 0.0f;
    if (tid < 128) {
        xsm[0][tid & 15][tid >> 4] = x[(size_t)b0 * NIN + tid];          // ts = 0
        xnext = x[(size_t)NBATCH * NIN + b0 * NIN + tid];                // ts = 1
    }

    float c = 0.0f;

    for (int ts = 0; ts < T_SEQ; ++ts) {
        const int p = ts & 1;
        __syncthreads();                // BAR-A: hsm (h of ts-1) + xsm[p] visible

        float d0 = 0.0f, d1 = 0.0f, d2 = 0.0f, d3 = 0.0f;

        // recurrent part: 8 k-steps over hid
#pragma unroll
        for (int ks = 0; ks < 8; ++ks) {
            float v0 = hsm[ks * 8 + tg][g];
            float v1 = hsm[ks * 8 + tg + 4][g];
            uint32_t bh0, bl0, bh1, bl1;
            tf32_split(v0, bh0, bl0);
            tf32_split(v1, bh1, bl1);
            mma1688(d0, d1, d2, d3, ahi[ks][0], ahi[ks][1], ahi[ks][2], ahi[ks][3], bh0, bh1);
            mma1688(d0, d1, d2, d3, ahi[ks][0], ahi[ks][1], ahi[ks][2], ahi[ks][3], bl0, bl1);
            mma1688(d0, d1, d2, d3, alo[ks][0], alo[ks][1], alo[ks][2], alo[ks][3], bh0, bh1);
        }
        // input part: 2 k-steps over features
#pragma unroll
        for (int ks = 8; ks < 10; ++ks) {
            float v0 = xsm[p][(ks - 8) * 8 + tg][g];
            float v1 = xsm[p][(ks - 8) * 8 + tg + 4][g];
            uint32_t bh0, bl0, bh1, bl1;
            tf32_split(v0, bh0, bl0);
            tf32_split(v1, bh1, bl1);
            mma1688(d0, d1, d2, d3, ahi[ks][0], ahi[ks][1], ahi[ks][2], ahi[ks][3], bh0, bh1);
            mma1688(d0, d1, d2, d3, ahi[ks][0], ahi[ks][1], ahi[ks][2], ahi[ks][3], bl0, bl1);
            mma1688(d0, d1, d2, d3, alo[ks][0], alo[ks][1], alo[ks][2], alo[ks][3], bh0, bh1);
        }

        // write z tile: rows wid*16+g, wid*16+g+8; cols 2tg, 2tg+1
        *reinterpret_cast<float2*>(&zsm[wid * 16 + g][2 * tg])     = make_float2(d0, d1);
        *reinterpret_cast<float2*>(&zsm[wid * 16 + g + 8][2 * tg]) = make_float2(d2, d3);

        // x double-buffer: publish x(ts+1), fetch x(ts+2)
        if (tid < 128) {
            xsm[p ^ 1][tid & 15][tid >> 4] = xnext;
            int tn = (ts + 2 < T_SEQ) ? ts + 2 : T_SEQ - 1;
            xnext = x[(size_t)tn * NBATCH * NIN + b0 * NIN + tid];
        }

        __syncthreads();                // BAR-B: zsm visible

        // activation: one (batch, hid) cell per thread
        float zi = zsm[jj][bA]       + bias_i;
        float zf = zsm[64 + jj][bA]  + bias_f;
        float zg = zsm[128 + jj][bA] + bias_g;
        float zo = zsm[192 + jj][bA] + bias_o;
        float iv = sigf(zi);
        float fv = sigf(zf);
        float gv = tanhf_fast(zg);
        float ov = sigf(zo);
        c = fmaf(fv, c, iv * gv);
        float h = ov * tanhf_fast(c);
        hsm[jj][bA] = h;                // consumed after next BAR-A
        g_hist[(((size_t)ts * NBATCH + b0 + bA) * NHEAD + hd) * HID + jj] = h;
    }
}

// ============================================================================
// Epilogue: out[t,b,h] = dot(h, W_lin[h]) + b_lin[h]; lstm_out = sum over heads
// ============================================================================
__global__ __launch_bounds__(256) void lstm_epi_kernel(
    const float* __restrict__ W_lin,
    const float* __restrict__ b_lin,
    float* __restrict__ out,
    float* __restrict__ lstm_out)
{
    const int cell = blockIdx.x * 16 + (threadIdx.x >> 4);
    const int q    = threadIdx.x & 15;

    const float4* hist4 = reinterpret_cast<const float4*>(g_hist) + (size_t)cell * 128;
    float4 v[NHEAD];
#pragma unroll
    for (int h = 0; h < NHEAD; ++h) v[h] = hist4[h * 16 + q];

    float4 s = v[0];
#pragma unroll
    for (int h = 1; h < NHEAD; ++h) { s.x += v[h].x; s.y += v[h].y; s.z += v[h].z; s.w += v[h].w; }
    reinterpret_cast<float4*>(lstm_out)[(size_t)cell * 16 + q] = s;

    const float4* wl4 = reinterpret_cast<const float4*>(W_lin);
    float d[NHEAD];
#pragma unroll
    for (int h = 0; h < NHEAD; ++h) {
        float4 w = wl4[h * 16 + q];
        float acc = v[h].x * w.x;
        acc = fmaf(v[h].y, w.y, acc);
        acc = fmaf(v[h].z, w.z, acc);
        acc = fmaf(v[h].w, w.w, acc);
        d[h] = acc;
    }
#pragma unroll
    for (int off = 8; off > 0; off >>= 1) {
#pragma unroll
        for (int h = 0; h < NHEAD; ++h)
            d[h] += __shfl_xor_sync(0xFFFFFFFFu, d[h], off);
    }
    if (q == 0) {
#pragma unroll
        for (int h = 0; h < NHEAD; ++h)
            out[(size_t)cell * NHEAD + h] = d[h] + b_lin[h];
    }
}

extern "C" void kernel_launch(void* const* d_in, const int* in_sizes, int n_in,
                              void* d_out, int out_size) {
    const float* x     = (const float*)d_in[0];
    const float* W_ih  = (const float*)d_in[1];
    const float* W_hh  = (const float*)d_in[2];
    const float* b_ih  = (const float*)d_in[3];
    const float* b_hh  = (const float*)d_in[4];
    const float* W_lin = (const float*)d_in[5];
    const float* b_lin = (const float*)d_in[6];

    float* out      = (float*)d_out;                         // (T,B,H)
    float* lstm_out = out + (size_t)T_SEQ * NBATCH * NHEAD;  // (T,B,HID)

    lstm_rec_mma<<<NHEAD * (NBATCH / 8), 512>>>(x, W_ih, W_hh, b_ih, b_hh);
    lstm_epi_kernel<<<(T_SEQ * NBATCH) / 16, 256>>>(W_lin, b_lin, out, lstm_out);
}

// round 7
// speedup vs baseline: 1.6776x; 1.6776x over previous
#include <cuda_runtime.h>
#include <cuda_bf16.h>
#include <cstdint>

#define T_SEQ 2048
#define NBATCH 64
#define NIN 16
#define NHEAD 8
#define HID 64
#define NGATE 256

// h history scratch (device global; no runtime allocation)
__device__ float g_hist[(size_t)T_SEQ * NBATCH * NHEAD * HID];   // 256 MB

// ---- helpers ----
__device__ __forceinline__ uint32_t pack_bf16x2(__nv_bfloat16 a, __nv_bfloat16 b) {
    __nv_bfloat162 v; v.x = a; v.y = b;
    return *reinterpret_cast<uint32_t*>(&v);
}
__device__ __forceinline__ void split_bf16(float f, __nv_bfloat16& hi, __nv_bfloat16& lo) {
    hi = __float2bfloat16_rn(f);
    lo = __float2bfloat16_rn(f - __bfloat162float(hi));
}
__device__ __forceinline__ void mma16816(float& d0, float& d1, float& d2, float& d3,
                                         uint32_t a0, uint32_t a1, uint32_t a2, uint32_t a3,
                                         uint32_t b0, uint32_t b1) {
    asm volatile(
        "mma.sync.aligned.m16n8k16.row.col.f32.bf16.bf16.f32 "
        "{%0,%1,%2,%3},{%4,%5,%6,%7},{%8,%9},{%0,%1,%2,%3};"
        : "+f"(d0), "+f"(d1), "+f"(d2), "+f"(d3)
        : "r"(a0), "r"(a1), "r"(a2), "r"(a3), "r"(b0), "r"(b1));
}
__device__ __forceinline__ float sigf(float z) {
    return __fdividef(1.0f, 1.0f + __expf(-z));
}
__device__ __forceinline__ float tanhf_fast(float z) {
    return fmaf(2.0f, sigf(2.0f * z), -1.0f);
}

// ============================================================================
// Recurrent kernel, bf16 m16n8k16 tensor-core version.
// Grid: 64 CTAs = head(8) x batch-group(8). Block: 512 (16 warps).
// Warp w owns gate-row tile [w*16, w*16+16). Per step, per warp:
//   4 recurrent k-steps (k16 over hid=64) + 1 input k-step (k16 over feat=16),
//   3 MMAs each (Whi·Bhi + Whi·Blo + Wlo·Bhi), fp32 accumulate = 15 HMMA.
// B-fragments read as packed bf16x2 straight from smem (split at the source
// by the 512 activation threads / 128 x-loader threads).
// ============================================================================
__global__ __launch_bounds__(512, 1) void lstm_rec_mma(
    const float* __restrict__ x,     // (T,B,16)
    const float* __restrict__ W_ih,  // (8,256,16)
    const float* __restrict__ W_hh,  // (8,256,64)
    const float* __restrict__ b_ih,  // (8,256)
    const float* __restrict__ b_hh)  // (8,256)
{
    const int tid  = threadIdx.x;
    const int wid  = tid >> 5;
    const int lane = tid & 31;
    const int g    = lane >> 2;     // A: row-in-tile ; B: batch column
    const int tg   = lane & 3;      // k sub-index
    const int hd   = blockIdx.x >> 3;
    const int b0   = (blockIdx.x & 7) * 8;

    // ---- A fragments (weights), bf16x2 hi/lo, register resident ----
    uint32_t ah_hi[4][4], ah_lo[4][4], ax_hi[4], ax_lo[4];
    {
        const float* Wh = W_hh + ((size_t)hd * NGATE + wid * 16) * HID;
#pragma unroll
        for (int ks = 0; ks < 4; ++ks) {
#pragma unroll
            for (int r = 0; r < 4; ++r) {
                int row = g + (r & 1) * 8;
                int kk  = 16 * ks + 2 * tg + (r >> 1) * 8;
                __nv_bfloat16 h0, l0, h1, l1;
                split_bf16(Wh[row * HID + kk],     h0, l0);
                split_bf16(Wh[row * HID + kk + 1], h1, l1);
                ah_hi[ks][r] = pack_bf16x2(h0, h1);
                ah_lo[ks][r] = pack_bf16x2(l0, l1);
            }
        }
        const float* Wi = W_ih + ((size_t)hd * NGATE + wid * 16) * NIN;
#pragma unroll
        for (int r = 0; r < 4; ++r) {
            int row = g + (r & 1) * 8;
            int kk  = 2 * tg + (r >> 1) * 8;
            __nv_bfloat16 h0, l0, h1, l1;
            split_bf16(Wi[row * NIN + kk],     h0, l0);
            split_bf16(Wi[row * NIN + kk + 1], h1, l1);
            ax_hi[r] = pack_bf16x2(h0, h1);
            ax_lo[r] = pack_bf16x2(l0, l1);
        }
    }

    // ---- consumer setup: thread = one (batch, hid) cell ----
    const int jj = tid & 63;
    const int bA = tid >> 6;
    const float bias_i = b_ih[hd * NGATE + jj]       + b_hh[hd * NGATE + jj];
    const float bias_f = b_ih[hd * NGATE + 64 + jj]  + b_hh[hd * NGATE + 64 + jj];
    const float bias_g = b_ih[hd * NGATE + 128 + jj] + b_hh[hd * NGATE + 128 + jj];
    const float bias_o = b_ih[hd * NGATE + 192 + jj] + b_hh[hd * NGATE + 192 + jj];

    // smem: padded strides for conflict-free bf16x2 LDS
    __shared__ __align__(4) __nv_bfloat16 hhi[8][72], hlo[8][72];      // [batch][k]
    __shared__ __align__(4) __nv_bfloat16 xhi[2][8][24], xlo[2][8][24];
    __shared__ __align__(8) float zsm[NGATE][10];                      // [gate_row][batch]

    for (int i = tid; i < 8 * 72; i += 512) { (&hhi[0][0])[i] = __float2bfloat16(0.0f); (&hlo[0][0])[i] = __float2bfloat16(0.0f); }

    // x loaders: 128 threads cover x[t, b0..b0+7, 0..15]
    float xnext = 0.0f;
    if (tid < 128) {
        int xb = tid >> 4, xf = tid & 15;
        __nv_bfloat16 h0, l0;
        split_bf16(x[((size_t)b0 + xb) * NIN + xf], h0, l0);           // ts = 0
        xhi[0][xb][xf] = h0; xlo[0][xb][xf] = l0;
        xnext = x[(size_t)NBATCH * NIN + (b0 + xb) * NIN + xf];        // ts = 1
    }

    float c = 0.0f;

    for (int ts = 0; ts < T_SEQ; ++ts) {
        const int p = ts & 1;
        __syncthreads();                 // BAR-A: hhi/hlo (ts-1) + xhi/xlo[p] visible

        float d0 = 0.0f, d1 = 0.0f, d2 = 0.0f, d3 = 0.0f;

        // recurrent: 4 k-steps over hid
#pragma unroll
        for (int ks = 0; ks < 4; ++ks) {
            uint32_t bh0 = *reinterpret_cast<const uint32_t*>(&hhi[g][16 * ks + 2 * tg]);
            uint32_t bh1 = *reinterpret_cast<const uint32_t*>(&hhi[g][16 * ks + 2 * tg + 8]);
            uint32_t bl0 = *reinterpret_cast<const uint32_t*>(&hlo[g][16 * ks + 2 * tg]);
            uint32_t bl1 = *reinterpret_cast<const uint32_t*>(&hlo[g][16 * ks + 2 * tg + 8]);
            mma16816(d0, d1, d2, d3, ah_hi[ks][0], ah_hi[ks][1], ah_hi[ks][2], ah_hi[ks][3], bh0, bh1);
            mma16816(d0, d1, d2, d3, ah_hi[ks][0], ah_hi[ks][1], ah_hi[ks][2], ah_hi[ks][3], bl0, bl1);
            mma16816(d0, d1, d2, d3, ah_lo[ks][0], ah_lo[ks][1], ah_lo[ks][2], ah_lo[ks][3], bh0, bh1);
        }
        // input: 1 k-step over features
        {
            uint32_t bh0 = *reinterpret_cast<const uint32_t*>(&xhi[p][g][2 * tg]);
            uint32_t bh1 = *reinterpret_cast<const uint32_t*>(&xhi[p][g][2 * tg + 8]);
            uint32_t bl0 = *reinterpret_cast<const uint32_t*>(&xlo[p][g][2 * tg]);
            uint32_t bl1 = *reinterpret_cast<const uint32_t*>(&xlo[p][g][2 * tg + 8]);
            mma16816(d0, d1, d2, d3, ax_hi[0], ax_hi[1], ax_hi[2], ax_hi[3], bh0, bh1);
            mma16816(d0, d1, d2, d3, ax_hi[0], ax_hi[1], ax_hi[2], ax_hi[3], bl0, bl1);
            mma16816(d0, d1, d2, d3, ax_lo[0], ax_lo[1], ax_lo[2], ax_lo[3], bh0, bh1);
        }

        // z tile: rows wid*16+g, +8; cols 2tg, 2tg+1
        *reinterpret_cast<float2*>(&zsm[wid * 16 + g][2 * tg])     = make_float2(d0, d1);
        *reinterpret_cast<float2*>(&zsm[wid * 16 + g + 8][2 * tg]) = make_float2(d2, d3);

        // x double-buffer: publish x(ts+1), fetch x(ts+2)
        if (tid < 128) {
            int xb = tid >> 4, xf = tid & 15;
            __nv_bfloat16 h0, l0;
            split_bf16(xnext, h0, l0);
            xhi[p ^ 1][xb][xf] = h0; xlo[p ^ 1][xb][xf] = l0;
            int tn = (ts + 2 < T_SEQ) ? ts + 2 : T_SEQ - 1;
            xnext = x[(size_t)tn * NBATCH * NIN + (b0 + xb) * NIN + xf];
        }

        __syncthreads();                 // BAR-B: zsm visible, h reads complete

        // activation: one (batch, hid) cell per thread; split h at the source
        float zi = zsm[jj][bA]       + bias_i;
        float zf = zsm[64 + jj][bA]  + bias_f;
        float zg = zsm[128 + jj][bA] + bias_g;
        float zo = zsm[192 + jj][bA] + bias_o;
        float iv = sigf(zi);
        float fv = sigf(zf);
        float gv = tanhf_fast(zg);
        float ov = sigf(zo);
        c = fmaf(fv, c, iv * gv);
        float h = ov * tanhf_fast(c);
        __nv_bfloat16 hh, hl;
        split_bf16(h, hh, hl);
        hhi[bA][jj] = hh;
        hlo[bA][jj] = hl;
        g_hist[(((size_t)ts * NBATCH + b0 + bA) * NHEAD + hd) * HID + jj] = h;
    }
}

// ============================================================================
// Epilogue: out[t,b,h] = dot(h, W_lin[h]) + b_lin[h]; lstm_out = sum over heads
// ============================================================================
__global__ __launch_bounds__(256) void lstm_epi_kernel(
    const float* __restrict__ W_lin,
    const float* __restrict__ b_lin,
    float* __restrict__ out,
    float* __restrict__ lstm_out)
{
    const int cell = blockIdx.x * 16 + (threadIdx.x >> 4);
    const int q    = threadIdx.x & 15;

    const float4* hist4 = reinterpret_cast<const float4*>(g_hist) + (size_t)cell * 128;
    float4 v[NHEAD];
#pragma unroll
    for (int h = 0; h < NHEAD; ++h) v[h] = hist4[h * 16 + q];

    float4 s = v[0];
#pragma unroll
    for (int h = 1; h < NHEAD; ++h) { s.x += v[h].x; s.y += v[h].y; s.z += v[h].z; s.w += v[h].w; }
    reinterpret_cast<float4*>(lstm_out)[(size_t)cell * 16 + q] = s;

    const float4* wl4 = reinterpret_cast<const float4*>(W_lin);
    float d[NHEAD];
#pragma unroll
    for (int h = 0; h < NHEAD; ++h) {
        float4 w = wl4[h * 16 + q];
        float acc = v[h].x * w.x;
        acc = fmaf(v[h].y, w.y, acc);
        acc = fmaf(v[h].z, w.z, acc);
        acc = fmaf(v[h].w, w.w, acc);
        d[h] = acc;
    }
#pragma unroll
    for (int off = 8; off > 0; off >>= 1) {
#pragma unroll
        for (int h = 0; h < NHEAD; ++h)
            d[h] += __shfl_xor_sync(0xFFFFFFFFu, d[h], off);
    }
    if (q == 0) {
#pragma unroll
        for (int h = 0; h < NHEAD; ++h)
            out[(size_t)cell * NHEAD + h] = d[h] + b_lin[h];
    }
}

extern "C" void kernel_launch(void* const* d_in, const int* in_sizes, int n_in,
                              void* d_out, int out_size) {
    const float* x     = (const float*)d_in[0];
    const float* W_ih  = (const float*)d_in[1];
    const float* W_hh  = (const float*)d_in[2];
    const float* b_ih  = (const float*)d_in[3];
    const float* b_hh  = (const float*)d_in[4];
    const float* W_lin = (const float*)d_in[5];
    const float* b_lin = (const float*)d_in[6];

    float* out      = (float*)d_out;                         // (T,B,H)
    float* lstm_out = out + (size_t)T_SEQ * NBATCH * NHEAD;  // (T,B,HID)

    lstm_rec_mma<<<NHEAD * (NBATCH / 8), 512>>>(x, W_ih, W_hh, b_ih, b_hh);
    lstm_epi_kernel<<<(T_SEQ * NBATCH) / 16, 256>>>(W_lin, b_lin, out, lstm_out);
}

// round 8
// speedup vs baseline: 2.0592x; 1.2275x over previous
#include <cuda_runtime.h>
#include <cuda_bf16.h>
#include <cstdint>

#define T_SEQ 2048
#define NBATCH 64
#define NIN 16
#define NHEAD 8
#define HID 64
#define NGATE 256

// h history scratch (device global; no runtime allocation)
__device__ float g_hist[(size_t)T_SEQ * NBATCH * NHEAD * HID];   // 256 MB

// ---- helpers ----
__device__ __forceinline__ uint32_t pack_bf16x2(__nv_bfloat16 a, __nv_bfloat16 b) {
    __nv_bfloat162 v; v.x = a; v.y = b;
    return *reinterpret_cast<uint32_t*>(&v);
}
__device__ __forceinline__ void split_bf16(float f, __nv_bfloat16& hi, __nv_bfloat16& lo) {
    hi = __float2bfloat16_rn(f);
    lo = __float2bfloat16_rn(f - __bfloat162float(hi));
}
__device__ __forceinline__ void mma16816(float& d0, float& d1, float& d2, float& d3,
                                         uint32_t a0, uint32_t a1, uint32_t a2, uint32_t a3,
                                         uint32_t b0, uint32_t b1) {
    asm volatile(
        "mma.sync.aligned.m16n8k16.row.col.f32.bf16.bf16.f32 "
        "{%0,%1,%2,%3},{%4,%5,%6,%7},{%8,%9},{%0,%1,%2,%3};"
        : "+f"(d0), "+f"(d1), "+f"(d2), "+f"(d3)
        : "r"(a0), "r"(a1), "r"(a2), "r"(a3), "r"(b0), "r"(b1));
}
__device__ __forceinline__ float tanha(float x) {
    float y; asm("tanh.approx.f32 %0, %1;" : "=f"(y) : "f"(x)); return y;
}
__device__ __forceinline__ float siga(float z) {          // 1 MUFU sigmoid
    return fmaf(0.5f, tanha(0.5f * z), 0.5f);
}

// ============================================================================
// Recurrent kernel, bf16 m16n8k16, gate-permuted tiles + register transpose.
// Grid: 64 CTAs = head(8) x batch-group(8). Block: 512 (16 warps).
// Warp w's m16 tile rows = permuted gate rows: tile row r -> global row
// (r&3)*64 + (4w + (r>>2)), so the warp owns ALL FOUR gates of cells
// j in [4w, 4w+4) x 8 batches. After 15 HMMA (3-term bf16 split, fp32 acc,
// bias pre-seeded), a 4-shuffle butterfly transpose gives each lane
// (zi,zf,zg,zo) of one cell -> in-warp activation, ONE barrier per step.
// ============================================================================
__global__ __launch_bounds__(512, 1) void lstm_rec_mma(
    const float* __restrict__ x,     // (T,B,16)
    const float* __restrict__ W_ih,  // (8,256,16)
    const float* __restrict__ W_hh,  // (8,256,64)
    const float* __restrict__ b_ih,  // (8,256)
    const float* __restrict__ b_hh)  // (8,256)
{
    const int tid  = threadIdx.x;
    const int wid  = tid >> 5;
    const int lane = tid & 31;
    const int g    = lane >> 2;       // fragment group id
    const int tg   = lane & 3;
    const int G    = g & 3;           // gate of this lane's A rows
    const int q    = g >> 2;          // j-slot base (0 or 1)
    const int hd   = blockIdx.x >> 3;
    const int b0   = (blockIdx.x & 7) * 8;

    // my two A rows: (gate G, j0) and (gate G, j0+2)
    const int j0 = 4 * wid + q;
    const int rowA = G * 64 + j0;          // local gate row, tile rows g / g+8
    const int rowB = rowA + 2;

    // ---- A fragments (weights), bf16x2 hi/lo, register resident ----
    uint32_t ah_hi[4][4], ah_lo[4][4], ax_hi[4], ax_lo[4];
    {
        const float* WhA = W_hh + ((size_t)hd * NGATE + rowA) * HID;
        const float* WhB = W_hh + ((size_t)hd * NGATE + rowB) * HID;
#pragma unroll
        for (int ks = 0; ks < 4; ++ks) {
#pragma unroll
            for (int r = 0; r < 4; ++r) {
                const float* Wr = (r & 1) ? WhB : WhA;
                int kk = 16 * ks + 2 * tg + (r >> 1) * 8;
                __nv_bfloat16 h0, l0, h1, l1;
                split_bf16(Wr[kk],     h0, l0);
                split_bf16(Wr[kk + 1], h1, l1);
                ah_hi[ks][r] = pack_bf16x2(h0, h1);
                ah_lo[ks][r] = pack_bf16x2(l0, l1);
            }
        }
        const float* WiA = W_ih + ((size_t)hd * NGATE + rowA) * NIN;
        const float* WiB = W_ih + ((size_t)hd * NGATE + rowB) * NIN;
#pragma unroll
        for (int r = 0; r < 4; ++r) {
            const float* Wr = (r & 1) ? WiB : WiA;
            int kk = 2 * tg + (r >> 1) * 8;
            __nv_bfloat16 h0, l0, h1, l1;
            split_bf16(Wr[kk],     h0, l0);
            split_bf16(Wr[kk + 1], h1, l1);
            ax_hi[r] = pack_bf16x2(h0, h1);
            ax_lo[r] = pack_bf16x2(l0, l1);
        }
    }
    // accumulator bias seeds (row bias, same for both batch cols)
    const float biasA = b_ih[hd * NGATE + rowA] + b_hh[hd * NGATE + rowA];
    const float biasB = b_ih[hd * NGATE + rowB] + b_hh[hd * NGATE + rowB];

    // my output cell after transpose
    const int jc = 4 * wid + q + 2 * (G >> 1);
    const int bc = 2 * tg + (G & 1);
    float* gptr = g_hist + ((size_t)(b0 + bc) * NHEAD + hd) * HID + jc;

    // smem: double-buffered h (hi/lo bf16) and x
    __shared__ __align__(4) __nv_bfloat16 hhi[2][8][72], hlo[2][8][72];
    __shared__ __align__(4) __nv_bfloat16 xhi[2][8][24], xlo[2][8][24];

    for (int i = tid; i < 2 * 8 * 72; i += 512) {
        (&hhi[0][0][0])[i] = __float2bfloat16(0.0f);
        (&hlo[0][0][0])[i] = __float2bfloat16(0.0f);
    }

    // x loaders: 128 threads cover x[t, b0..b0+7, 0..15]
    float xnext = 0.0f;
    if (tid < 128) {
        int xb = tid >> 4, xf = tid & 15;
        __nv_bfloat16 h0, l0;
        split_bf16(x[((size_t)b0 + xb) * NIN + xf], h0, l0);           // ts = 0
        xhi[0][xb][xf] = h0; xlo[0][xb][xf] = l0;
        xnext = x[(size_t)NBATCH * NIN + (b0 + xb) * NIN + xf];        // ts = 1
    }

    float c = 0.0f;
    const unsigned FULL = 0xFFFFFFFFu;

    for (int ts = 0; ts < T_SEQ; ++ts) {
        const int p = ts & 1;
        __syncthreads();                 // h(ts-1) in buf p, x(ts) in buf p visible

        float d0 = biasA, d1 = biasA, d2 = biasB, d3 = biasB;

        // recurrent: 4 k-steps over hid
#pragma unroll
        for (int ks = 0; ks < 4; ++ks) {
            uint32_t bh0 = *reinterpret_cast<const uint32_t*>(&hhi[p][g][16 * ks + 2 * tg]);
            uint32_t bh1 = *reinterpret_cast<const uint32_t*>(&hhi[p][g][16 * ks + 2 * tg + 8]);
            uint32_t bl0 = *reinterpret_cast<const uint32_t*>(&hlo[p][g][16 * ks + 2 * tg]);
            uint32_t bl1 = *reinterpret_cast<const uint32_t*>(&hlo[p][g][16 * ks + 2 * tg + 8]);
            mma16816(d0, d1, d2, d3, ah_hi[ks][0], ah_hi[ks][1], ah_hi[ks][2], ah_hi[ks][3], bh0, bh1);
            mma16816(d0, d1, d2, d3, ah_hi[ks][0], ah_hi[ks][1], ah_hi[ks][2], ah_hi[ks][3], bl0, bl1);
            mma16816(d0, d1, d2, d3, ah_lo[ks][0], ah_lo[ks][1], ah_lo[ks][2], ah_lo[ks][3], bh0, bh1);
        }
        // input: 1 k-step over features
        {
            uint32_t bh0 = *reinterpret_cast<const uint32_t*>(&xhi[p][g][2 * tg]);
            uint32_t bh1 = *reinterpret_cast<const uint32_t*>(&xhi[p][g][2 * tg + 8]);
            uint32_t bl0 = *reinterpret_cast<const uint32_t*>(&xlo[p][g][2 * tg]);
            uint32_t bl1 = *reinterpret_cast<const uint32_t*>(&xlo[p][g][2 * tg + 8]);
            mma16816(d0, d1, d2, d3, ax_hi[0], ax_hi[1], ax_hi[2], ax_hi[3], bh0, bh1);
            mma16816(d0, d1, d2, d3, ax_hi[0], ax_hi[1], ax_hi[2], ax_hi[3], bl0, bl1);
            mma16816(d0, d1, d2, d3, ax_lo[0], ax_lo[1], ax_lo[2], ax_lo[3], bh0, bh1);
        }

        // x double-buffer: publish x(ts+1), fetch x(ts+2) (off critical path)
        if (tid < 128) {
            int xb = tid >> 4, xf = tid & 15;
            __nv_bfloat16 h0, l0;
            split_bf16(xnext, h0, l0);
            xhi[p ^ 1][xb][xf] = h0; xlo[p ^ 1][xb][xf] = l0;
            int tn = (ts + 2 < T_SEQ) ? ts + 2 : T_SEQ - 1;
            xnext = x[(size_t)tn * NBATCH * NIN + (b0 + xb) * NIN + xf];
        }

        // ---- 4x4 butterfly transpose over gate bits (lane xor 4, xor 8) ----
        {
            float a0 = (G & 1) ? d0 : d1;
            float a1 = (G & 1) ? d2 : d3;
            a0 = __shfl_xor_sync(FULL, a0, 4);
            a1 = __shfl_xor_sync(FULL, a1, 4);
            if (G & 1) { d0 = a0; d2 = a1; } else { d1 = a0; d3 = a1; }
            float e0 = (G & 2) ? d0 : d2;
            float e1 = (G & 2) ? d1 : d3;
            e0 = __shfl_xor_sync(FULL, e0, 8);
            e1 = __shfl_xor_sync(FULL, e1, 8);
            if (G & 2) { d0 = e0; d1 = e1; } else { d2 = e0; d3 = e1; }
        }
        // now d0=zi, d1=zf, d2=zg, d3=zo for cell (jc, bc)

        float iv = siga(d0);
        float fv = siga(d1);
        float gv = tanha(d2);
        float ov = siga(d3);
        c = fmaf(fv, c, iv * gv);
        float h = ov * tanha(c);

        __nv_bfloat16 hh, hl;
        split_bf16(h, hh, hl);
        hhi[p ^ 1][bc][jc] = hh;
        hlo[p ^ 1][bc][jc] = hl;
        gptr[(size_t)ts * (NBATCH * NHEAD * HID)] = h;
        // loop-top barrier publishes buf p^1 for step ts+1
    }
}

// ============================================================================
// Epilogue: out[t,b,h] = dot(h, W_lin[h]) + b_lin[h]; lstm_out = sum over heads
// ============================================================================
__global__ __launch_bounds__(256) void lstm_epi_kernel(
    const float* __restrict__ W_lin,
    const float* __restrict__ b_lin,
    float* __restrict__ out,
    float* __restrict__ lstm_out)
{
    const int cell = blockIdx.x * 16 + (threadIdx.x >> 4);
    const int q    = threadIdx.x & 15;

    const float4* hist4 = reinterpret_cast<const float4*>(g_hist) + (size_t)cell * 128;
    float4 v[NHEAD];
#pragma unroll
    for (int h = 0; h < NHEAD; ++h) v[h] = hist4[h * 16 + q];

    float4 s = v[0];
#pragma unroll
    for (int h = 1; h < NHEAD; ++h) { s.x += v[h].x; s.y += v[h].y; s.z += v[h].z; s.w += v[h].w; }
    reinterpret_cast<float4*>(lstm_out)[(size_t)cell * 16 + q] = s;

    const float4* wl4 = reinterpret_cast<const float4*>(W_lin);
    float d[NHEAD];
#pragma unroll
    for (int h = 0; h < NHEAD; ++h) {
        float4 w = wl4[h * 16 + q];
        float acc = v[h].x * w.x;
        acc = fmaf(v[h].y, w.y, acc);
        acc = fmaf(v[h].z, w.z, acc);
        acc = fmaf(v[h].w, w.w, acc);
        d[h] = acc;
    }
#pragma unroll
    for (int off = 8; off > 0; off >>= 1) {
#pragma unroll
        for (int h = 0; h < NHEAD; ++h)
            d[h] += __shfl_xor_sync(0xFFFFFFFFu, d[h], off);
    }
    if (q == 0) {
#pragma unroll
        for (int h = 0; h < NHEAD; ++h)
            out[(size_t)cell * NHEAD + h] = d[h] + b_lin[h];
    }
}

extern "C" void kernel_launch(void* const* d_in, const int* in_sizes, int n_in,
                              void* d_out, int out_size) {
    const float* x     = (const float*)d_in[0];
    const float* W_ih  = (const float*)d_in[1];
    const float* W_hh  = (const float*)d_in[2];
    const float* b_ih  = (const float*)d_in[3];
    const float* b_hh  = (const float*)d_in[4];
    const float* W_lin = (const float*)d_in[5];
    const float* b_lin = (const float*)d_in[6];

    float* out      = (float*)d_out;                         // (T,B,H)
    float* lstm_out = out + (size_t)T_SEQ * NBATCH * NHEAD;  // (T,B,HID)

    lstm_rec_mma<<<NHEAD * (NBATCH / 8), 512>>>(x, W_ih, W_hh, b_ih, b_hh);
    lstm_epi_kernel<<<(T_SEQ * NBATCH) / 16, 256>>>(W_lin, b_lin, out, lstm_out);
}